// round 4
// baseline (speedup 1.0000x reference)
#include <cuda_runtime.h>

// PZCell biquad, warp-per-row parallel scan, two sequential half-row tiles.
// y[t] = b0 x[t] + b1 x[t-1] + b2 x[t-2] - a1 y[t-1] - a2 y[t-2]   (den == 1)
// Each half: 32 lanes x 32 steps in a padded warp-private SMEM tile.
//   load (coalesced) -> Phase A zero-state recurrence in place ->
//   Kogge-Stone affine lane scan (T = M^32) -> entry states
//   (half 2 folds in half-1 exit via M^(32*lane)) ->
//   Phase C homogeneous add in place -> store (coalesced).

namespace {
constexpr int T_LEN  = 2048;
constexpr int B_ROWS = 4096;
constexpr int HALF   = 1024;               // timesteps per half-tile
constexpr int L      = 32;                 // chunk per lane
constexpr int PITCH  = 36;                 // floats per chunk (9 x 16B, odd -> conflict-free)
constexpr int RPB    = 4;                  // rows (warps) per block
constexpr int THREADS = 32 * RPB;
constexpr int ROW_SMEM = 32 * PITCH;       // 1152 floats
constexpr int SMEM_BYTES = RPB * ROW_SMEM * (int)sizeof(float);  // 18432
}

struct Coef {
    float a1, a2, A2, Bc, b0, b1, b2;
};

// process one 1024-step half. Returns exit state (y[last], y[last-1]) in (Px,Py).
template <int H>
__device__ __forceinline__ void half_pass(
    const float* __restrict__ xr, float* __restrict__ yr, float* sb,
    int lane, const Coef& c, float& Px, float& Py)
{
    float* myc = sb + lane * PITCH;

    // ---- coalesced load: 8 x float4 per lane ----
    #pragma unroll
    for (int k = 0; k < 8; ++k) {
        float4 v = *reinterpret_cast<const float4*>(xr + k * 128 + lane * 4);
        int chunk = k * 4 + (lane >> 3);
        int off   = (lane & 7) * 4;
        *reinterpret_cast<float4*>(sb + chunk * PITCH + off) = v;
    }
    __syncwarp();

    // ---- boundary x[-1], x[-2] ----
    float x1, x2;
    if (lane > 0) {
        x1 = sb[(lane - 1) * PITCH + L - 1];
        x2 = sb[(lane - 1) * PITCH + L - 2];
    } else if (H == 0) {
        x1 = 0.f; x2 = 0.f;
    } else {
        x1 = xr[-1]; x2 = xr[-2];   // tail of previous half (gmem, L2-hot)
    }

    // ---- Phase A: zero-entry-state recurrence in place ----
    float p = 0.f, q = 0.f;
    #pragma unroll
    for (int g = 0; g < L / 4; ++g) {
        float4 xv = *reinterpret_cast<float4*>(myc + 4 * g);
        float u0 = fmaf(c.b0, xv.x, fmaf(c.b1, x1,   c.b2 * x2));
        float u1 = fmaf(c.b0, xv.y, fmaf(c.b1, xv.x, c.b2 * x1));
        float u2 = fmaf(c.b0, xv.z, fmaf(c.b1, xv.y, c.b2 * xv.x));
        float u3 = fmaf(c.b0, xv.w, fmaf(c.b1, xv.z, c.b2 * xv.y));
        x2 = xv.z; x1 = xv.w;
        float w1 = fmaf(-c.a1, u0, u1);
        float w3 = fmaf(-c.a1, u2, u3);
        float yA = fmaf(-c.a1, p,  fmaf(-c.a2, q,  u0));
        float yB = fmaf( c.A2, p,  fmaf( c.Bc, q,  w1));
        float yC = fmaf(-c.a1, yB, fmaf(-c.a2, yA, u2));
        float yD = fmaf( c.A2, yB, fmaf( c.Bc, yA, w3));
        p = yD; q = yC;
        *reinterpret_cast<float4*>(myc + 4 * g) = make_float4(yA, yB, yC, yD);
    }

    // ---- T = M^32 via 5 squarings ----
    float m00 = -c.a1, m01 = -c.a2, m10 = 1.f, m11 = 0.f;
    #pragma unroll
    for (int i = 0; i < 5; ++i) {
        float t00 = m00*m00 + m01*m10, t01 = m00*m01 + m01*m11;
        float t10 = m10*m00 + m11*m10, t11 = m10*m01 + m11*m11;
        m00 = t00; m01 = t01; m10 = t10; m11 = t11;
    }

    // ---- affine Kogge-Stone scan; also build A = (M^32)^lane (half 2 only) ----
    float A00 = 1.f, A01 = 0.f, A10 = 0.f, A11 = 1.f;  // per-lane M^(32*lane)
    float vx = p, vy = q;
    #pragma unroll
    for (int i = 0; i < 5; ++i) {
        float ox = __shfl_up_sync(0xffffffffu, vx, 1u << i);
        float oy = __shfl_up_sync(0xffffffffu, vy, 1u << i);
        if (lane >= (1 << i)) {
            vx = fmaf(m00, ox, fmaf(m01, oy, vx));
            vy = fmaf(m10, ox, fmaf(m11, oy, vy));
        }
        if (H == 1 && ((lane >> i) & 1)) {   // A *= m (powers commute)
            float n00 = m00*A00 + m01*A10, n01 = m00*A01 + m01*A11;
            float n10 = m10*A00 + m11*A10, n11 = m10*A01 + m11*A11;
            A00 = n00; A01 = n01; A10 = n10; A11 = n11;
        }
        if (i < 4) {
            float t00 = m00*m00 + m01*m10, t01 = m00*m01 + m01*m11;
            float t10 = m10*m00 + m11*m10, t11 = m10*m01 + m11*m11;
            m00 = t00; m01 = t01; m10 = t10; m11 = t11;
        }
    }

    // entry state of this lane's chunk
    float ex = __shfl_up_sync(0xffffffffu, vx, 1);
    float ey = __shfl_up_sync(0xffffffffu, vy, 1);
    if (lane == 0) { ex = 0.f; ey = 0.f; }
    if (H == 1) {   // fold in half-1 exit state P
        ex = fmaf(A00, Px, fmaf(A01, Py, ex));
        ey = fmaf(A10, Px, fmaf(A11, Py, ey));
    }

    // exit state of this half = inclusive scan at lane 31 (+ M^1024 * P for half 2)
    float gx = __shfl_sync(0xffffffffu, vx, 31);
    float gy = __shfl_sync(0xffffffffu, vy, 31);
    if (H == 1) {
        // M^1024 = m (currently M^512) squared
        float t00 = m00*m00 + m01*m10, t01 = m00*m01 + m01*m11;
        float t10 = m10*m00 + m11*m10, t11 = m10*m01 + m11*m11;
        gx = fmaf(t00, Px, fmaf(t01, Py, gx));
        gy = fmaf(t10, Px, fmaf(t11, Py, gy));
    }
    Px = gx; Py = gy;

    // ---- Phase C: homogeneous response added in place ----
    float h1 = ex, h2 = ey;
    #pragma unroll
    for (int g = 0; g < L / 4; ++g) {
        float hA = fmaf(-c.a1, h1, -c.a2 * h2);
        float hB = fmaf( c.A2, h1,  c.Bc * h2);
        float hC = fmaf(-c.a1, hB, -c.a2 * hA);
        float hD = fmaf( c.A2, hB,  c.Bc * hA);
        h2 = hC; h1 = hD;
        float4 zv = *reinterpret_cast<float4*>(myc + 4 * g);
        zv.x += hA; zv.y += hB; zv.z += hC; zv.w += hD;
        *reinterpret_cast<float4*>(myc + 4 * g) = zv;
    }
    __syncwarp();

    // ---- coalesced store ----
    #pragma unroll
    for (int k = 0; k < 8; ++k) {
        int chunk = k * 4 + (lane >> 3);
        int off   = (lane & 7) * 4;
        float4 v = *reinterpret_cast<float4*>(sb + chunk * PITCH + off);
        *reinterpret_cast<float4*>(yr + k * 128 + lane * 4) = v;
    }
    __syncwarp();
}

__global__ void __launch_bounds__(THREADS, 7)
pz4_kernel(const float* __restrict__ x, const float* __restrict__ gain_ri,
           const float* __restrict__ poles_ri, const float* __restrict__ zeros_ri,
           float* __restrict__ out)
{
    extern __shared__ float sbuf[];
    const int lane = threadIdx.x & 31;
    const int w    = threadIdx.x >> 5;
    const int row  = blockIdx.x * RPB + w;
    const float* xr = x   + (long)row * T_LEN;
    float*       yr = out + (long)row * T_LEN;
    float* sb = sbuf + w * ROW_SMEM;

    Coef c;
    {
        const float gr = gain_ri[0],  gi = gain_ri[1];
        const float pr0 = poles_ri[0], pi0 = poles_ri[1];
        const float pr1 = poles_ri[2], pi1 = poles_ri[3];
        const float zr0 = zeros_ri[0], zi0 = zeros_ri[1];
        const float zr1 = zeros_ri[2], zi1 = zeros_ri[3];
        c.a1 = -(pr0 + pr1);
        c.a2 = pr0 * pr1 - pi0 * pi1;
        const float zc1r = -(zr0 + zr1), zc1i = -(zi0 + zi1);
        const float zc2r = zr0 * zr1 - zi0 * zi1;
        const float zc2i = zr0 * zi1 + zi0 * zr1;
        c.b0 = gr;
        c.b1 = gr * zc1r - gi * zc1i;
        c.b2 = gr * zc2r - gi * zc2i;
        c.A2 = c.a1 * c.a1 - c.a2;
        c.Bc = c.a1 * c.a2;
    }

    float Px = 0.f, Py = 0.f;
    half_pass<0>(xr,        yr,        sb, lane, c, Px, Py);
    half_pass<1>(xr + HALF, yr + HALF, sb, lane, c, Px, Py);
}

extern "C" void kernel_launch(void* const* d_in, const int* in_sizes, int n_in,
                              void* d_out, int out_size) {
    (void)in_sizes; (void)n_in; (void)out_size;
    const float* x        = (const float*)d_in[0];
    const float* gain_ri  = (const float*)d_in[1];
    const float* poles_ri = (const float*)d_in[2];
    const float* zeros_ri = (const float*)d_in[3];
    float* out = (float*)d_out;

    cudaFuncSetAttribute(pz4_kernel, cudaFuncAttributeMaxDynamicSharedMemorySize, SMEM_BYTES);
    pz4_kernel<<<B_ROWS / RPB, THREADS, SMEM_BYTES>>>(x, gain_ri, poles_ri, zeros_ri, out);
}

// round 5
// speedup vs baseline: 1.0753x; 1.0753x over previous
#include <cuda_runtime.h>

// PZCell biquad, warp-per-row parallel scan, cp.async double-buffered halves.
// y[t] = b0 x[t] + b1 x[t-1] + b2 x[t-2] - a1 y[t-1] - a2 y[t-2]   (den == 1)
// Per warp: two 1024-step halves, each 32 lanes x 32 steps in an XOR-swizzled
// 32x32 SMEM tile (4KB). Both halves' loads issued up front via cp.async.

namespace {
constexpr int T_LEN  = 2048;
constexpr int B_ROWS = 4096;
constexpr int HALF   = 1024;
constexpr int L      = 32;                 // steps per lane per half
constexpr int RPB    = 2;                  // rows (warps) per block
constexpr int THREADS = 32 * RPB;
constexpr int TILE   = 32 * 32;            // floats per buffer (4KB)
constexpr int WARP_SMEM = 2 * TILE;        // double buffer
constexpr int SMEM_BYTES = RPB * WARP_SMEM * (int)sizeof(float);  // 16384
}

// float4-granule XOR swizzle: float index of granule g (0..7) in chunk c (0..31)
__device__ __forceinline__ int swz(int c, int g) {
    return c * 32 + ((g ^ (c & 7)) << 2);
}

__device__ __forceinline__ void cp_async16(float* dst, const float* src) {
    unsigned s = (unsigned)__cvta_generic_to_shared(dst);
    asm volatile("cp.async.cg.shared.global [%0], [%1], 16;" :: "r"(s), "l"(src));
}
__device__ __forceinline__ void cp_commit() { asm volatile("cp.async.commit_group;"); }
__device__ __forceinline__ void cp_wait1()  { asm volatile("cp.async.wait_group 1;" ::: "memory"); }
__device__ __forceinline__ void cp_wait0()  { asm volatile("cp.async.wait_group 0;" ::: "memory"); }

struct Coef { float a1, a2, A2, Bc, b0, b1, b2; };

// one 1024-step half over tile sb. Px,Py = running row exit state.
template <int H>
__device__ __forceinline__ void half_pass(
    float* __restrict__ yr, float* sb, int lane, const Coef& c,
    float& Px, float& Py, float bx1, float bx2)
{
    // ---- boundary x[-1], x[-2] ----
    float x1, x2;
    if (lane > 0) {
        x1 = sb[(lane - 1) * 32 + ((7 ^ ((lane - 1) & 7)) << 2) + 3];  // f=31
        x2 = sb[(lane - 1) * 32 + ((7 ^ ((lane - 1) & 7)) << 2) + 2];  // f=30
    } else if (H == 0) {
        x1 = 0.f; x2 = 0.f;
    } else {
        x1 = bx1; x2 = bx2;        // saved tail of half 1's x
    }

    // ---- Phase A: zero-entry-state recurrence in place ----
    float p = 0.f, q = 0.f;
    #pragma unroll
    for (int g = 0; g < L / 4; ++g) {
        float4 xv = *reinterpret_cast<float4*>(sb + swz(lane, g));
        float u0 = fmaf(c.b0, xv.x, fmaf(c.b1, x1,   c.b2 * x2));
        float u1 = fmaf(c.b0, xv.y, fmaf(c.b1, xv.x, c.b2 * x1));
        float u2 = fmaf(c.b0, xv.z, fmaf(c.b1, xv.y, c.b2 * xv.x));
        float u3 = fmaf(c.b0, xv.w, fmaf(c.b1, xv.z, c.b2 * xv.y));
        x2 = xv.z; x1 = xv.w;
        float w1 = fmaf(-c.a1, u0, u1);
        float w3 = fmaf(-c.a1, u2, u3);
        float yA = fmaf(-c.a1, p,  fmaf(-c.a2, q,  u0));
        float yB = fmaf( c.A2, p,  fmaf( c.Bc, q,  w1));
        float yC = fmaf(-c.a1, yB, fmaf(-c.a2, yA, u2));
        float yD = fmaf( c.A2, yB, fmaf( c.Bc, yA, w3));
        p = yD; q = yC;
        *reinterpret_cast<float4*>(sb + swz(lane, g)) = make_float4(yA, yB, yC, yD);
    }

    // ---- T = M^32 via 5 squarings, M = [[-a1,-a2],[1,0]] ----
    float m00 = -c.a1, m01 = -c.a2, m10 = 1.f, m11 = 0.f;
    #pragma unroll
    for (int i = 0; i < 5; ++i) {
        float t00 = m00*m00 + m01*m10, t01 = m00*m01 + m01*m11;
        float t10 = m10*m00 + m11*m10, t11 = m10*m01 + m11*m11;
        m00 = t00; m01 = t01; m10 = t10; m11 = t11;
    }

    // ---- affine Kogge-Stone scan; build A = (M^32)^lane for half 2 ----
    float A00 = 1.f, A01 = 0.f, A10 = 0.f, A11 = 1.f;
    float vx = p, vy = q;
    #pragma unroll
    for (int i = 0; i < 5; ++i) {
        float ox = __shfl_up_sync(0xffffffffu, vx, 1u << i);
        float oy = __shfl_up_sync(0xffffffffu, vy, 1u << i);
        if (lane >= (1 << i)) {
            vx = fmaf(m00, ox, fmaf(m01, oy, vx));
            vy = fmaf(m10, ox, fmaf(m11, oy, vy));
        }
        if (H == 1 && ((lane >> i) & 1)) {
            float n00 = m00*A00 + m01*A10, n01 = m00*A01 + m01*A11;
            float n10 = m10*A00 + m11*A10, n11 = m10*A01 + m11*A11;
            A00 = n00; A01 = n01; A10 = n10; A11 = n11;
        }
        if (i < 4) {
            float t00 = m00*m00 + m01*m10, t01 = m00*m01 + m01*m11;
            float t10 = m10*m00 + m11*m10, t11 = m10*m01 + m11*m11;
            m00 = t00; m01 = t01; m10 = t10; m11 = t11;
        }
    }

    float ex = __shfl_up_sync(0xffffffffu, vx, 1);
    float ey = __shfl_up_sync(0xffffffffu, vy, 1);
    if (lane == 0) { ex = 0.f; ey = 0.f; }
    if (H == 1) {   // fold half-1 exit state into entries
        ex = fmaf(A00, Px, fmaf(A01, Py, ex));
        ey = fmaf(A10, Px, fmaf(A11, Py, ey));
    }

    float gx = __shfl_sync(0xffffffffu, vx, 31);
    float gy = __shfl_sync(0xffffffffu, vy, 31);
    if (H == 1) {   // M^1024 = (M^512)^2 applied to half-1 exit
        float t00 = m00*m00 + m01*m10, t01 = m00*m01 + m01*m11;
        float t10 = m10*m00 + m11*m10, t11 = m10*m01 + m11*m11;
        gx = fmaf(t00, Px, fmaf(t01, Py, gx));
        gy = fmaf(t10, Px, fmaf(t11, Py, gy));
    }
    Px = gx; Py = gy;

    // ---- Phase C: add homogeneous response in place ----
    float h1 = ex, h2 = ey;
    #pragma unroll
    for (int g = 0; g < L / 4; ++g) {
        float hA = fmaf(-c.a1, h1, -c.a2 * h2);
        float hB = fmaf( c.A2, h1,  c.Bc * h2);
        float hC = fmaf(-c.a1, hB, -c.a2 * hA);
        float hD = fmaf( c.A2, hB,  c.Bc * hA);
        h2 = hC; h1 = hD;
        float4 zv = *reinterpret_cast<float4*>(sb + swz(lane, g));
        zv.x += hA; zv.y += hB; zv.z += hC; zv.w += hD;
        *reinterpret_cast<float4*>(sb + swz(lane, g)) = zv;
    }
    __syncwarp();

    // ---- coalesced store ----
    #pragma unroll
    for (int k = 0; k < 8; ++k) {
        int chunk = k * 4 + (lane >> 3);
        float4 v = *reinterpret_cast<float4*>(sb + swz(chunk, lane & 7));
        *reinterpret_cast<float4*>(yr + k * 128 + lane * 4) = v;
    }
    __syncwarp();
}

__global__ void __launch_bounds__(THREADS, 14)
pz5_kernel(const float* __restrict__ x, const float* __restrict__ gain_ri,
           const float* __restrict__ poles_ri, const float* __restrict__ zeros_ri,
           float* __restrict__ out)
{
    extern __shared__ float sbuf[];
    const int lane = threadIdx.x & 31;
    const int w    = threadIdx.x >> 5;
    const int row  = blockIdx.x * RPB + w;
    const float* xr = x   + (long)row * T_LEN;
    float*       yr = out + (long)row * T_LEN;
    float* sb = sbuf + w * WARP_SMEM;

    // ---- issue both halves' loads up front (two commit groups) ----
    #pragma unroll
    for (int k = 0; k < 8; ++k) {
        int chunk = k * 4 + (lane >> 3);
        cp_async16(sb + swz(chunk, lane & 7), xr + k * 128 + lane * 4);
    }
    cp_commit();
    #pragma unroll
    for (int k = 0; k < 8; ++k) {
        int chunk = k * 4 + (lane >> 3);
        cp_async16(sb + TILE + swz(chunk, lane & 7), xr + HALF + k * 128 + lane * 4);
    }
    cp_commit();

    // ---- coefficients (overlap with cp.async) ----
    Coef c;
    {
        const float gr = gain_ri[0],  gi = gain_ri[1];
        const float pr0 = poles_ri[0], pi0 = poles_ri[1];
        const float pr1 = poles_ri[2], pi1 = poles_ri[3];
        const float zr0 = zeros_ri[0], zi0 = zeros_ri[1];
        const float zr1 = zeros_ri[2], zi1 = zeros_ri[3];
        c.a1 = -(pr0 + pr1);
        c.a2 = pr0 * pr1 - pi0 * pi1;
        const float zc1r = -(zr0 + zr1), zc1i = -(zi0 + zi1);
        const float zc2r = zr0 * zr1 - zi0 * zi1;
        const float zc2i = zr0 * zi1 + zi0 * zr1;
        c.b0 = gr;
        c.b1 = gr * zc1r - gi * zc1i;
        c.b2 = gr * zc2r - gi * zc2i;
        c.A2 = c.a1 * c.a1 - c.a2;
        c.Bc = c.a1 * c.a2;
    }

    cp_wait1();          // half 1 resident
    __syncwarp();

    // snapshot half-1's x tail for half-2 boundary (before Phase A overwrites)
    // chunk 31: 31&7=7 -> granule 7 swizzles to 0 -> floats 31*32+0..3; f=31 -> +3
    float bx1 = sb[31 * 32 + 3];   // x[1023]
    float bx2 = sb[31 * 32 + 2];   // x[1022]

    float Px = 0.f, Py = 0.f;
    half_pass<0>(yr, sb, lane, c, Px, Py, 0.f, 0.f);

    cp_wait0();          // half 2 resident
    __syncwarp();
    half_pass<1>(yr + HALF, sb + TILE, lane, c, Px, Py, bx1, bx2);
}

extern "C" void kernel_launch(void* const* d_in, const int* in_sizes, int n_in,
                              void* d_out, int out_size) {
    (void)in_sizes; (void)n_in; (void)out_size;
    const float* x        = (const float*)d_in[0];
    const float* gain_ri  = (const float*)d_in[1];
    const float* poles_ri = (const float*)d_in[2];
    const float* zeros_ri = (const float*)d_in[3];
    float* out = (float*)d_out;

    cudaFuncSetAttribute(pz5_kernel, cudaFuncAttributeMaxDynamicSharedMemorySize, SMEM_BYTES);
    pz5_kernel<<<B_ROWS / RPB, THREADS, SMEM_BYTES>>>(x, gain_ri, poles_ri, zeros_ri, out);
}